// round 3
// baseline (speedup 1.0000x reference)
#include <cuda_runtime.h>
#include <math.h>

#define B_ 16
#define HW 4096          // 64*64
#define CD 32
#define DIMX 512
#define NSCALES 14
#define OUT_ELEMS (B_*DIMX*HW)   // 33554432

#define NBLK 296
#define NTHR 256
#define NWARP (NBLK*(NTHR/32))   // 2368

#define INV_SQRT32 0.17677669529663687f
#define ACOEF 70.710678118654755f   // 4*100/sqrt(32); p = sigmoid(-ACOEF*z)

__device__ float g_r0[B_*HW*CD];     // original projection (token-major b,p,d)
__device__ float g_r [B_*HW*CD];     // residual
__device__ float g_pool[2741760];    // pooled sums, scales 0..12 concatenated
__device__ float g_acc[NSCALES][34]; // [0..31]=sum p, [32]=sum H, [33]=sum commit
__device__ unsigned g_barcnt;
__device__ volatile unsigned g_bargen;

__constant__ int c_ph[13]   = {1,2,3,4,5,7,9,12,16,21,27,36,48};
__constant__ int c_poff[13] = {0,512,2560,7168,15360,28160,53248,94720,
                               168448,299520,525312,898560,1562112};

// ---------------------------------------------------------------- f32x2 helpers
__device__ __forceinline__ unsigned long long pk2(float x, float y) {
    unsigned long long r;
    asm("mov.b64 %0, {%1, %2};" : "=l"(r) : "f"(x), "f"(y));
    return r;
}
__device__ __forceinline__ unsigned long long fma2(unsigned long long a,
                                                   unsigned long long b,
                                                   unsigned long long c) {
    unsigned long long d;
    asm("fma.rn.f32x2 %0, %1, %2, %3;" : "=l"(d) : "l"(a), "l"(b), "l"(c));
    return d;
}
__device__ __forceinline__ void upk2(unsigned long long v, float& lo, float& hi) {
    asm("mov.b64 {%0, %1}, %2;" : "=f"(lo), "=f"(hi) : "l"(v));
}

// ---------------------------------------------------------------- grid barrier
__device__ __forceinline__ void gbar() {
    __threadfence();                 // release this thread's writes
    __syncthreads();
    if (threadIdx.x == 0) {
        unsigned gen = g_bargen;
        if (atomicAdd(&g_barcnt, 1u) == NBLK - 1) {
            g_barcnt = 0;
            __threadfence();
            g_bargen = gen + 1;
        } else {
            while (g_bargen == gen) __nanosleep(64);
        }
        __threadfence();             // acquire: invalidate this SM's L1
    }
    __syncthreads();
}

// ---------------------------------------------------------------- proj_in
// r[b,p,d] = sum_c x[b,c,p] * w_in[c,d] + b_in[d]   (FFMA2, 2 px/thread)
__global__ __launch_bounds__(128) void proj_in_kernel(
        const float* __restrict__ x,
        const float* __restrict__ w_in,
        const float* __restrict__ b_in) {
    extern __shared__ float s_w[];   // [512][32]
    int tid = threadIdx.x;
    for (int i = tid; i < DIMX * CD; i += 128) s_w[i] = w_in[i];
    __syncthreads();

    int b = blockIdx.x >> 4;
    int base = (blockIdx.x & 15) << 8;
    int p0 = base + tid, p1 = p0 + 128;
    const float* xp0 = x + ((size_t)b * DIMX) * HW + p0;
    const float* xp1 = x + ((size_t)b * DIMX) * HW + p1;

    unsigned long long a0[16], a1[16];
#pragma unroll
    for (int q = 0; q < 16; q++) {
        unsigned long long bi = pk2(b_in[2*q], b_in[2*q+1]);
        a0[q] = bi; a1[q] = bi;
    }

#pragma unroll 4
    for (int c = 0; c < DIMX; c++) {
        float f0 = xp0[(size_t)c * HW];
        float f1 = xp1[(size_t)c * HW];
        unsigned long long X0 = pk2(f0, f0);
        unsigned long long X1 = pk2(f1, f1);
        const ulonglong2* row = (const ulonglong2*)(s_w + c * CD);
#pragma unroll
        for (int r = 0; r < 8; r++) {
            ulonglong2 w2 = row[r];
            a0[2*r]   = fma2(X0, w2.x, a0[2*r]);
            a0[2*r+1] = fma2(X0, w2.y, a0[2*r+1]);
            a1[2*r]   = fma2(X1, w2.x, a1[2*r]);
            a1[2*r+1] = fma2(X1, w2.y, a1[2*r+1]);
        }
    }
    size_t o0 = ((size_t)(b * HW + p0)) * CD;
    size_t o1 = ((size_t)(b * HW + p1)) * CD;
#pragma unroll
    for (int k = 0; k < 8; k++) {
        ulonglong2 v0; v0.x = a0[2*k]; v0.y = a0[2*k+1];
        ulonglong2 v1; v1.x = a1[2*k]; v1.y = a1[2*k+1];
        ((ulonglong2*)(g_r0 + o0))[k] = v0;
        ((ulonglong2*)(g_r  + o0))[k] = v0;
        ((ulonglong2*)(g_r0 + o1))[k] = v1;
        ((ulonglong2*)(g_r  + o1))[k] = v1;
    }
}

// ---------------------------------------------------------------- pool phase
__device__ void pool_phase(int t, int gw, int lane, int tid) {
    int ph = c_ph[t], np = ph * ph, ntok = B_ * np;
    int base = c_poff[t];
    if (ntok >= 2048) {
        // one warp per token, direct store
        for (int tok = gw; tok < ntok; tok += NWARP) {
            int b = tok / np, ij = tok - b * np, i = ij / ph, j = ij - i * ph;
            int sh = (i * 64) / ph, eh = ((i + 1) * 64 + ph - 1) / ph;
            int sw = (j * 64) / ph, ew = ((j + 1) * 64 + ph - 1) / ph;
            const float* rb = g_r + ((size_t)(b * HW)) * CD + lane;
            float sum = 0.f;
            for (int y = sh; y < eh; y++) {
                const float* row = rb + (size_t)(y * 64) * CD;
                for (int x = sw; x < ew; x++) sum += row[(size_t)x * CD];
            }
            g_pool[base + tok * CD + lane] = sum;
        }
    } else {
        // sliced by region row, atomic accumulate (pool pre-zeroed)
        int S = 64 / ph + 2;
        int work = ntok * S;
        for (int w = gw; w < work; w += NWARP) {
            int tok = w / S, slice = w - tok * S;
            int b = tok / np, ij = tok - b * np, i = ij / ph, j = ij - i * ph;
            int sh = (i * 64) / ph, eh = ((i + 1) * 64 + ph - 1) / ph;
            int y = sh + slice;
            if (y < eh) {
                int sw = (j * 64) / ph, ew = ((j + 1) * 64 + ph - 1) / ph;
                const float* row = g_r + ((size_t)(b * HW + y * 64)) * CD + lane;
                float sum = 0.f;
                for (int x = sw; x < ew; x++) sum += row[(size_t)x * CD];
                atomicAdd(&g_pool[base + tok * CD + lane], sum);
            }
        }
        if (t == 1) {   // re-zero pool0 for the NEXT run (consumers done)
            for (int idx = blockIdx.x * NTHR + tid; idx < 512; idx += NBLK * NTHR)
                g_pool[idx] = 0.f;
        }
    }
}

// ---------------------------------------------------------------- up phase (r -= bilerp(sign(pool)))
__device__ void up_phase(int s, int gw, int lane, int tid,
                         int* s_i0, int* s_i1, float* s_f) {
    int ph = c_ph[s], np = ph * ph;
    if (tid < 64) {
        float src = ((float)tid + 0.5f) * (float)ph * 0.015625f - 0.5f;
        src = fminf(fmaxf(src, 0.f), (float)(ph - 1));
        int i0 = (int)src;
        s_i0[tid] = i0;
        s_i1[tid] = min(i0 + 1, ph - 1);
        s_f[tid]  = src - (float)i0;
    }
    __syncthreads();
    const float* pool = g_pool + c_poff[s];
    for (int pix = gw; pix < B_ * HW; pix += NWARP) {
        int b = pix >> 12, h = (pix >> 6) & 63, w = pix & 63;
        int i0 = s_i0[h], i1 = s_i1[h]; float fh = s_f[h];
        int j0 = s_i0[w], j1 = s_i1[w]; float fw = s_f[w];
        int tb = b * np;
        float p00 = pool[(tb + i0 * ph + j0) * CD + lane];
        float p01 = pool[(tb + i0 * ph + j1) * CD + lane];
        float p10 = pool[(tb + i1 * ph + j0) * CD + lane];
        float p11 = pool[(tb + i1 * ph + j1) * CD + lane];
        float s00 = p00 > 0.f ? 1.f : -1.f, s01 = p01 > 0.f ? 1.f : -1.f;
        float s10 = p10 > 0.f ? 1.f : -1.f, s11 = p11 > 0.f ? 1.f : -1.f;
        float top = (1.f - fw) * s00 + fw * s01;
        float bot = (1.f - fw) * s10 + fw * s11;
        float v = INV_SQRT32 * ((1.f - fh) * top + fh * bot);
        g_r[(size_t)pix * CD + lane] -= v;
    }
}

// ---------------------------------------------------------------- loss accumulation
__device__ void loss_accum(int s, int gw, int lane) {
    int ph = (s < 13) ? c_ph[s] : 64;
    int np = ph * ph, ntok = B_ * np;
    const float* src = (s < 13) ? (g_pool + c_poff[s]) : g_r;
    float pa = 0.f, ha = 0.f, ca = 0.f;
    for (int tok = gw; tok < ntok; tok += NWARP) {
        float ir;
        if (s < 13) {
            int b = tok / np, ij = tok - b * np, i = ij / ph, j = ij - i * ph;
            int ah = ((i + 1) * 64 + ph - 1) / ph - (i * 64) / ph;
            int aw = ((j + 1) * 64 + ph - 1) / ph - (j * 64) / ph;
            ir = src[tok * CD + lane] / (float)(ah * aw);
        } else {
            ir = src[(size_t)tok * CD + lane];
        }
        float n2 = ir * ir;
#pragma unroll
        for (int o = 16; o > 0; o >>= 1) n2 += __shfl_xor_sync(~0u, n2, o);
        float z = ir / fmaxf(sqrtf(n2), 1e-12f);
        float p = 1.f / (1.f + expf(ACOEF * z));
        float H = -(p * logf(p + 1e-8f) + (1.f - p) * logf(1.f - p + 1e-8f));
        float qv = (z > 0.f) ? INV_SQRT32 : -INV_SQRT32;
        float dz = z - qv;
        pa += p; ha += H; ca += dz * dz;
    }
#pragma unroll
    for (int o = 16; o > 0; o >>= 1) {
        ha += __shfl_xor_sync(~0u, ha, o);
        ca += __shfl_xor_sync(~0u, ca, o);
    }
    atomicAdd(&g_acc[s][lane], pa);
    if (lane == 0) { atomicAdd(&g_acc[s][32], ha); atomicAdd(&g_acc[s][33], ca); }
}

// ---------------------------------------------------------------- persistent scale loop
__global__ __launch_bounds__(NTHR, 2) void msq_kernel(float* __restrict__ loss_out) {
    __shared__ int s_i0[64], s_i1[64];
    __shared__ float s_f[64];
    int tid = threadIdx.x, lane = tid & 31;
    int gw = blockIdx.x * (NTHR / 32) + (tid >> 5);

    pool_phase(0, gw, lane, tid);            // pool0 (zero invariant from prev run/BSS)

    for (int s = 0; s <= 12; s++) {
        gbar();                               // pool[s] visible
        up_phase(s, gw, lane, tid, s_i0, s_i1, s_f);
        loss_accum(s, gw, lane);
        if (s + 1 <= 6) {                     // pre-zero next atomic-path pool
            int sz = 512 * c_ph[s+1] * c_ph[s+1];
            int off = c_poff[s+1];
            for (int idx = blockIdx.x * NTHR + tid; idx < sz; idx += NBLK * NTHR)
                g_pool[off + idx] = 0.f;
        }
        gbar();                               // r updated, visible
        if (s <= 11) pool_phase(s + 1, gw, lane, tid);
    }
    loss_accum(13, gw, lane);                 // scale 13: pool == r itself
    gbar();

    if (blockIdx.x == 0) {
        if (tid < 32) {
            for (int s = 0; s < NSCALES; s++) {
                int ph = (s < 13) ? c_ph[s] : 64;
                float n = (float)(B_ * ph * ph);
                float ap = g_acc[s][lane] / n;
                float H = -(ap * logf(ap + 1e-8f) + (1.f - ap) * logf(1.f - ap + 1e-8f));
#pragma unroll
                for (int o = 16; o > 0; o >>= 1) H += __shfl_xor_sync(~0u, H, o);
                if (lane == 0) {
                    float ps = g_acc[s][32] / n;
                    float cm = g_acc[s][33] / (n * 32.f);
                    loss_out[s] = (ps - H) * (0.1f / 100.f) + 0.25f * cm;
                }
            }
        }
        __syncthreads();
        for (int idx = tid; idx < NSCALES * 34; idx += NTHR)   // re-zero for next run
            ((float*)g_acc)[idx] = 0.f;
    }
}

// ---------------------------------------------------------------- proj_out
// qo = r0 - r + sign(r)/sqrt32 ; out[b,c,p] = sum_d qo[d]*w_out[d,c] + b_out[c]
__global__ __launch_bounds__(128) void proj_out_kernel(
        const float* __restrict__ w_out,
        const float* __restrict__ b_out,
        float* __restrict__ out) {
    extern __shared__ float s[];
    float* s_wt = s;                 // transposed: [c][d]
    float* s_b  = s + DIMX * CD;
    int tid = threadIdx.x;
    for (int idx = tid; idx < DIMX * CD; idx += 128) {
        int c = idx >> 5, d = idx & 31;
        s_wt[c * CD + d] = w_out[d * DIMX + c];
    }
    for (int i = tid; i < DIMX; i += 128) s_b[i] = b_out[i];
    __syncthreads();

    int b = blockIdx.x >> 4;
    int base = (blockIdx.x & 15) << 8;
    int p0 = base + tid, p1 = p0 + 128;
    size_t o0 = ((size_t)(b * HW + p0)) * CD;
    size_t o1 = ((size_t)(b * HW + p1)) * CD;

    unsigned long long Q0[16], Q1[16];
#pragma unroll
    for (int k = 0; k < 8; k++) {
        float4 a  = ((const float4*)(g_r0 + o0))[k];
        float4 r  = ((const float4*)(g_r  + o0))[k];
        float qx = (r.x > 0.f) ? INV_SQRT32 : -INV_SQRT32;
        float qy = (r.y > 0.f) ? INV_SQRT32 : -INV_SQRT32;
        float qz = (r.z > 0.f) ? INV_SQRT32 : -INV_SQRT32;
        float qw = (r.w > 0.f) ? INV_SQRT32 : -INV_SQRT32;
        Q0[2*k]   = pk2(a.x - r.x + qx, a.y - r.y + qy);
        Q0[2*k+1] = pk2(a.z - r.z + qz, a.w - r.w + qw);
        float4 a1 = ((const float4*)(g_r0 + o1))[k];
        float4 r1 = ((const float4*)(g_r  + o1))[k];
        qx = (r1.x > 0.f) ? INV_SQRT32 : -INV_SQRT32;
        qy = (r1.y > 0.f) ? INV_SQRT32 : -INV_SQRT32;
        qz = (r1.z > 0.f) ? INV_SQRT32 : -INV_SQRT32;
        qw = (r1.w > 0.f) ? INV_SQRT32 : -INV_SQRT32;
        Q1[2*k]   = pk2(a1.x - r1.x + qx, a1.y - r1.y + qy);
        Q1[2*k+1] = pk2(a1.z - r1.z + qz, a1.w - r1.w + qw);
    }

    float* op0 = out + ((size_t)b * DIMX) * HW + p0;
    float* op1 = out + ((size_t)b * DIMX) * HW + p1;

#pragma unroll 2
    for (int c = 0; c < DIMX; c++) {
        const ulonglong2* wrow = (const ulonglong2*)(s_wt + c * CD);
        unsigned long long a0e = 0, a0o = 0, a1e = 0, a1o = 0;
#pragma unroll
        for (int r = 0; r < 8; r++) {
            ulonglong2 W = wrow[r];
            a0e = fma2(Q0[2*r],   W.x, a0e);
            a0o = fma2(Q0[2*r+1], W.y, a0o);
            a1e = fma2(Q1[2*r],   W.x, a1e);
            a1o = fma2(Q1[2*r+1], W.y, a1o);
        }
        float lo, hi, s0, s1;
        upk2(a0e, lo, hi); s0 = lo + hi;
        upk2(a0o, lo, hi); s0 += lo + hi;
        upk2(a1e, lo, hi); s1 = lo + hi;
        upk2(a1o, lo, hi); s1 += lo + hi;
        float bias = s_b[c];
        op0[(size_t)c * HW] = s0 + bias;
        op1[(size_t)c * HW] = s1 + bias;
    }
}

// ---------------------------------------------------------------- launch
extern "C" void kernel_launch(void* const* d_in, const int* in_sizes, int n_in,
                              void* d_out, int out_size) {
    const float* x     = (const float*)d_in[0];
    const float* w_in  = (const float*)d_in[1];
    const float* b_in  = (const float*)d_in[2];
    const float* w_out = (const float*)d_in[3];
    const float* b_out = (const float*)d_in[4];
    float* out = (float*)d_out;

    cudaFuncSetAttribute(proj_in_kernel,  cudaFuncAttributeMaxDynamicSharedMemorySize, 66 * 1024);
    cudaFuncSetAttribute(proj_out_kernel, cudaFuncAttributeMaxDynamicSharedMemorySize, 68 * 1024);

    proj_in_kernel<<<256, 128, 64 * 1024>>>(x, w_in, b_in);
    msq_kernel<<<NBLK, NTHR>>>(out + OUT_ELEMS);
    proj_out_kernel<<<256, 128, 68 * 1024>>>(w_out, b_out, out);
}

// round 6
// speedup vs baseline: 1.4293x; 1.4293x over previous
#include <cuda_runtime.h>
#include <math.h>

#define B_ 16
#define HW 4096          // 64*64
#define CD 32
#define DIMX 512
#define NSCALES 14
#define NPIX (B_*HW)                 // 65536
#define OUT_ELEMS (B_*DIMX*HW)       // 33554432

#define INV_SQRT32 0.17677669529663687f
#define ACOEF 70.710678118654755f    // 4*100/sqrt(32); p = sigmoid(-ACOEF*z)

__device__ float g_r0[NPIX*CD];      // original projection (token-major)
__device__ float g_r [NPIX*CD];      // residual
__device__ float g_part[2][NPIX*CD]; // split-K partials for proj_in
__device__ float g_pool[2741760];    // pooled sums, scales 0..12
__device__ float g_acc[NSCALES][34]; // [0..31]=sum p, [32]=sum H, [33]=sum commit

__constant__ int c_ph[13]   = {1,2,3,4,5,7,9,12,16,21,27,36,48};
__constant__ int c_poff[13] = {0,512,2560,7168,15360,28160,53248,94720,
                               168448,299520,525312,898560,1562112};
#define SLICED_POOL_FLOATS 94720     // scales 0..6 use atomic slicing

// ---------------------------------------------------------------- f32x2 helpers
__device__ __forceinline__ unsigned long long pk2(float x, float y) {
    unsigned long long r;
    asm("mov.b64 %0, {%1, %2};" : "=l"(r) : "f"(x), "f"(y));
    return r;
}
__device__ __forceinline__ unsigned long long fma2(unsigned long long a,
                                                   unsigned long long b,
                                                   unsigned long long c) {
    unsigned long long d;
    asm("fma.rn.f32x2 %0, %1, %2, %3;" : "=l"(d) : "l"(a), "l"(b), "l"(c));
    return d;
}
__device__ __forceinline__ void upk2(unsigned long long v, float& lo, float& hi) {
    asm("mov.b64 {%0, %1}, %2;" : "=f"(lo), "=f"(hi) : "l"(v));
}

// ---------------------------------------------------------------- init (every replay)
__global__ void init_kernel() {
    int t = blockIdx.x * blockDim.x + threadIdx.x;
    for (int i = t; i < SLICED_POOL_FLOATS; i += gridDim.x * blockDim.x)
        g_pool[i] = 0.f;
    if (t < NSCALES * 34) ((float*)g_acc)[t] = 0.f;
}

// ---------------------------------------------------------------- proj_in GEMM (split-K=2)
__global__ __launch_bounds__(256) void gemm_in_kernel(
        const float* __restrict__ x, const float* __restrict__ w_in) {
    __shared__ float s_w[256 * CD];           // 32KB c-chunk of weights
    int tid = threadIdx.x;
    int kc = blockIdx.x & 1;
    int pg = blockIdx.x >> 1;
    const float* wsrc = w_in + kc * 256 * CD;
    for (int i = tid; i < 256 * CD; i += 256) s_w[i] = wsrc[i];
    __syncthreads();

    int px = pg * 256 + tid;
    int b = px >> 12, pl = px & 4095;
    const float* xp = x + (size_t)b * (DIMX * HW) + (size_t)(kc * 256) * HW + pl;

    unsigned long long a[16];
#pragma unroll
    for (int i = 0; i < 16; i++) a[i] = 0ull;

#pragma unroll 4
    for (int c = 0; c < 256; c++) {
        float f = xp[(size_t)c * HW];
        unsigned long long X = pk2(f, f);
        const ulonglong2* row = (const ulonglong2*)(s_w + c * CD);
#pragma unroll
        for (int r = 0; r < 8; r++) {
            ulonglong2 w2 = row[r];
            a[2*r]   = fma2(X, w2.x, a[2*r]);
            a[2*r+1] = fma2(X, w2.y, a[2*r+1]);
        }
    }
    ulonglong2* o = (ulonglong2*)(g_part[kc] + (size_t)px * CD);
#pragma unroll
    for (int k = 0; k < 8; k++) {
        ulonglong2 v; v.x = a[2*k]; v.y = a[2*k+1];
        o[k] = v;
    }
}

// combine: r0 = r = part0 + part1 + bias   (fully coalesced float4)
__global__ __launch_bounds__(256) void combine_kernel(const float* __restrict__ b_in) {
    int idx = blockIdx.x * 256 + threadIdx.x;         // float4 index, grid 2048
    float4 p0 = __ldg((const float4*)g_part[0] + idx);
    float4 p1 = __ldg((const float4*)g_part[1] + idx);
    float4 bi = __ldg((const float4*)b_in + (idx & 7));
    float4 v;
    v.x = p0.x + p1.x + bi.x;
    v.y = p0.y + p1.y + bi.y;
    v.z = p0.z + p1.z + bi.z;
    v.w = p0.w + p1.w + bi.w;
    ((float4*)g_r0)[idx] = v;
    ((float4*)g_r )[idx] = v;
}

// ---------------------------------------------------------------- per-token loss math (lane=d)
__device__ __forceinline__ void loss_token(float ir, float& pa, float& ha, float& ca) {
    float n2 = ir * ir;
#pragma unroll
    for (int o = 16; o > 0; o >>= 1) n2 += __shfl_xor_sync(~0u, n2, o);
    float z = ir / fmaxf(sqrtf(n2), 1e-12f);
    float p = 1.f / (1.f + expf(ACOEF * z));
    float H = -(p * logf(p + 1e-8f) + (1.f - p) * logf(1.f - p + 1e-8f));
    float qv = (z > 0.f) ? INV_SQRT32 : -INV_SQRT32;
    float dz = z - qv;
    pa += p; ha += H; ca += dz * dz;
}

// ---------------------------------------------------------------- pool, big scales (warp/token, fused loss)
__global__ __launch_bounds__(256) void pool_big_kernel(int s) {
    __shared__ float s_red[34];
    int tid = threadIdx.x, lane = tid & 31;
    if (tid < 34) s_red[tid] = 0.f;
    __syncthreads();

    int ph = c_ph[s], np = ph * ph, ntok = B_ * np;
    int base = c_poff[s];
    int gw = blockIdx.x * 8 + (tid >> 5);
    int nw = gridDim.x * 8;

    float pa = 0.f, ha = 0.f, ca = 0.f;
    for (int tok = gw; tok < ntok; tok += nw) {
        int b = tok / np, ij = tok - b * np, i = ij / ph, j = ij - i * ph;
        int sh = (i * 64) / ph, eh = ((i + 1) * 64 + ph - 1) / ph;
        int sw = (j * 64) / ph, ew = ((j + 1) * 64 + ph - 1) / ph;
        const float* rb = g_r + ((size_t)(b * HW)) * CD + lane;
        float sum = 0.f;
        for (int y = sh; y < eh; y++) {
            const float* row = rb + (size_t)(y * 64) * CD;
#pragma unroll 2
            for (int x = sw; x < ew; x++) sum += row[(size_t)x * CD];
        }
        g_pool[base + tok * CD + lane] = sum;
        loss_token(sum / (float)((eh - sh) * (ew - sw)), pa, ha, ca);
    }
#pragma unroll
    for (int o = 16; o > 0; o >>= 1) {
        ha += __shfl_xor_sync(~0u, ha, o);
        ca += __shfl_xor_sync(~0u, ca, o);
    }
    atomicAdd(&s_red[lane], pa);
    if (lane == 0) { atomicAdd(&s_red[32], ha); atomicAdd(&s_red[33], ca); }
    __syncthreads();
    if (tid < 34) atomicAdd(&g_acc[s][tid], s_red[tid]);
}

// ---------------------------------------------------------------- pool, small scales (row slices, atomic)
// S must be >= max region rows = floor(64/ph)+2 (guard y<eh makes excess free)
__global__ __launch_bounds__(256) void pool_small_kernel(int s, int S) {
    int tid = threadIdx.x, lane = tid & 31;
    int ph = c_ph[s], np = ph * ph, ntok = B_ * np;
    int base = c_poff[s];
    int w = blockIdx.x * 8 + (tid >> 5);
    if (w >= ntok * S) return;
    int tok = w / S, slice = w - tok * S;
    int b = tok / np, ij = tok - b * np, i = ij / ph, j = ij - i * ph;
    int sh = (i * 64) / ph, eh = ((i + 1) * 64 + ph - 1) / ph;
    int y = sh + slice;
    if (y >= eh) return;
    int sw = (j * 64) / ph, ew = ((j + 1) * 64 + ph - 1) / ph;
    const float* row = g_r + ((size_t)(b * HW + y * 64)) * CD + lane;
    float sum = 0.f;
#pragma unroll 4
    for (int x = sw; x < ew; x++) sum += row[(size_t)x * CD];
    atomicAdd(&g_pool[base + tok * CD + lane], sum);
}

// ---------------------------------------------------------------- up: r -= bilerp(sign(pool)); fused loss for sliced scales
// grid MUST be 4096 blocks: 4096*8 warps * 2 px/warp = 65536 px
__global__ __launch_bounds__(256) void up_kernel(int s, int sliced) {
    __shared__ int s_i0[64], s_i1[64];
    __shared__ float s_f[64];
    __shared__ float s_red[34];
    int tid = threadIdx.x, lane = tid & 31;
    int ph = c_ph[s], np = ph * ph;

    if (tid < 64) {
        float src = ((float)tid + 0.5f) * (float)ph * 0.015625f - 0.5f;
        src = fminf(fmaxf(src, 0.f), (float)(ph - 1));
        int i0 = (int)src;
        s_i0[tid] = i0;
        s_i1[tid] = min(i0 + 1, ph - 1);
        s_f[tid]  = src - (float)i0;
    }
    if (tid < 34) s_red[tid] = 0.f;
    __syncthreads();

    const float* pool = g_pool + c_poff[s];
    int gw = blockIdx.x * 8 + (tid >> 5);          // 32768 warps total

    if (sliced) {
        int ntok = B_ * np;
        if (gw < ntok) {
            int tok = gw;
            int b = tok / np, ij = tok - b * np, i = ij / ph, j = ij - i * ph;
            int ah = ((i + 1) * 64 + ph - 1) / ph - (i * 64) / ph;
            int aw = ((j + 1) * 64 + ph - 1) / ph - (j * 64) / ph;
            float ir = pool[tok * CD + lane] / (float)(ah * aw);
            float pa = 0.f, ha = 0.f, ca = 0.f;
            loss_token(ir, pa, ha, ca);
#pragma unroll
            for (int o = 16; o > 0; o >>= 1) {
                ha += __shfl_xor_sync(~0u, ha, o);
                ca += __shfl_xor_sync(~0u, ca, o);
            }
            atomicAdd(&s_red[lane], pa);
            if (lane == 0) { atomicAdd(&s_red[32], ha); atomicAdd(&s_red[33], ca); }
        }
    }

    // bilerp: warp handles 2 pixels; lane = (px half, d-pair)
    int px = gw * 2 + (lane >> 4);
    int dp = lane & 15;
    int b = px >> 12, h = (px >> 6) & 63, w = px & 63;
    int i0 = s_i0[h], i1 = s_i1[h]; float fh = s_f[h];
    int j0 = s_i0[w], j1 = s_i1[w]; float fw = s_f[w];
    int tb = b * np;
    float2 p00 = *(const float2*)(pool + (tb + i0 * ph + j0) * CD + 2 * dp);
    float2 p01 = *(const float2*)(pool + (tb + i0 * ph + j1) * CD + 2 * dp);
    float2 p10 = *(const float2*)(pool + (tb + i1 * ph + j0) * CD + 2 * dp);
    float2 p11 = *(const float2*)(pool + (tb + i1 * ph + j1) * CD + 2 * dp);
    float s00x = p00.x > 0.f ? 1.f : -1.f, s00y = p00.y > 0.f ? 1.f : -1.f;
    float s01x = p01.x > 0.f ? 1.f : -1.f, s01y = p01.y > 0.f ? 1.f : -1.f;
    float s10x = p10.x > 0.f ? 1.f : -1.f, s10y = p10.y > 0.f ? 1.f : -1.f;
    float s11x = p11.x > 0.f ? 1.f : -1.f, s11y = p11.y > 0.f ? 1.f : -1.f;
    float tx = (1.f - fw) * s00x + fw * s01x;
    float ty = (1.f - fw) * s00y + fw * s01y;
    float bx = (1.f - fw) * s10x + fw * s11x;
    float by = (1.f - fw) * s10y + fw * s11y;
    float vx = INV_SQRT32 * ((1.f - fh) * tx + fh * bx);
    float vy = INV_SQRT32 * ((1.f - fh) * ty + fh * by);
    float2* rp = (float2*)(g_r + (size_t)px * CD + 2 * dp);
    float2 rv = *rp;
    rv.x -= vx; rv.y -= vy;
    *rp = rv;

    if (sliced) {
        __syncthreads();
        if (tid < 34) atomicAdd(&g_acc[s][tid], s_red[tid]);
    }
}

// ---------------------------------------------------------------- loss for scale 13 (identity, reads r)
__global__ __launch_bounds__(256) void loss13_kernel() {
    __shared__ float s_red[34];
    int tid = threadIdx.x, lane = tid & 31;
    if (tid < 34) s_red[tid] = 0.f;
    __syncthreads();
    int gw = blockIdx.x * 8 + (tid >> 5);
    int nw = gridDim.x * 8;
    float pa = 0.f, ha = 0.f, ca = 0.f;
    for (int tok = gw; tok < NPIX; tok += nw) {
        float ir = g_r[(size_t)tok * CD + lane];
        loss_token(ir, pa, ha, ca);
    }
#pragma unroll
    for (int o = 16; o > 0; o >>= 1) {
        ha += __shfl_xor_sync(~0u, ha, o);
        ca += __shfl_xor_sync(~0u, ca, o);
    }
    atomicAdd(&s_red[lane], pa);
    if (lane == 0) { atomicAdd(&s_red[32], ha); atomicAdd(&s_red[33], ca); }
    __syncthreads();
    if (tid < 34) atomicAdd(&g_acc[13][tid], s_red[tid]);
}

// ---------------------------------------------------------------- finalize losses
__global__ void finalize_kernel(float* __restrict__ loss_out) {
    int s = threadIdx.x >> 5;
    int lane = threadIdx.x & 31;
    if (s >= NSCALES) return;
    int ph = (s < 13) ? c_ph[s] : 64;
    float n = (float)(B_ * ph * ph);
    float ap = g_acc[s][lane] / n;
    float H = -(ap * logf(ap + 1e-8f) + (1.f - ap) * logf(1.f - ap + 1e-8f));
#pragma unroll
    for (int o = 16; o > 0; o >>= 1) H += __shfl_xor_sync(~0u, H, o);
    if (lane == 0) {
        float ps = g_acc[s][32] / n;
        float cm = g_acc[s][33] / (n * 32.f);
        loss_out[s] = (ps - H) * (0.1f / 100.f) + 0.25f * cm;
    }
}

// ---------------------------------------------------------------- proj_out GEMM (split-N=2)
// qo = r0 - r + sign(r)/sqrt32 ; out[b,c,p] = sum_d qo[d]*w_out[d,c] + b_out[c]
__global__ __launch_bounds__(256) void gemm_out_kernel(
        const float* __restrict__ w_out,
        const float* __restrict__ b_out,
        float* __restrict__ out) {
    __shared__ float s_wt[256 * 36];    // padded transpose [c][d], 36KB
    __shared__ float s_b[256];
    int tid = threadIdx.x;
    int kc = blockIdx.x & 1;
    int pg = blockIdx.x >> 1;
    int c0 = kc * 256;
    for (int i = tid; i < 256 * CD; i += 256) {
        int d = i >> 8, c = i & 255;
        s_wt[c * 36 + d] = w_out[d * DIMX + c0 + c];
    }
    if (tid < 256) s_b[tid] = b_out[c0 + tid];
    __syncthreads();

    int px = pg * 256 + tid;
    int b = px >> 12, pl = px & 4095;
    size_t o = (size_t)px * CD;

    unsigned long long Q[16];
#pragma unroll
    for (int k = 0; k < 8; k++) {
        float4 a = __ldg((const float4*)(g_r0 + o) + k);
        float4 r = ((const float4*)(g_r + o))[k];
        float qx = (r.x > 0.f) ? INV_SQRT32 : -INV_SQRT32;
        float qy = (r.y > 0.f) ? INV_SQRT32 : -INV_SQRT32;
        float qz = (r.z > 0.f) ? INV_SQRT32 : -INV_SQRT32;
        float qw = (r.w > 0.f) ? INV_SQRT32 : -INV_SQRT32;
        Q[2*k]   = pk2(a.x - r.x + qx, a.y - r.y + qy);
        Q[2*k+1] = pk2(a.z - r.z + qz, a.w - r.w + qw);
    }

    float* op = out + (size_t)b * (DIMX * HW) + (size_t)c0 * HW + pl;
#pragma unroll 2
    for (int c = 0; c < 256; c++) {
        const ulonglong2* wrow = (const ulonglong2*)(s_wt + c * 36);
        unsigned long long ae = 0, ao = 0;
#pragma unroll
        for (int r = 0; r < 8; r++) {
            ulonglong2 W = wrow[r];
            ae = fma2(Q[2*r],   W.x, ae);
            ao = fma2(Q[2*r+1], W.y, ao);
        }
        float lo, hi, sum;
        upk2(ae, lo, hi); sum = lo + hi;
        upk2(ao, lo, hi); sum += lo + hi;
        op[(size_t)c * HW] = sum + s_b[c];
    }
}

// ---------------------------------------------------------------- launch
extern "C" void kernel_launch(void* const* d_in, const int* in_sizes, int n_in,
                              void* d_out, int out_size) {
    const float* x     = (const float*)d_in[0];
    const float* w_in  = (const float*)d_in[1];
    const float* b_in  = (const float*)d_in[2];
    const float* w_out = (const float*)d_in[3];
    const float* b_out = (const float*)d_in[4];
    float* out = (float*)d_out;

    static const int sched[13] = {1,2,3,4,5,7,9,12,16,21,27,36,48};

    init_kernel<<<370, 256>>>();
    gemm_in_kernel<<<512, 256>>>(x, w_in);
    combine_kernel<<<2048, 256>>>(b_in);

    for (int s = 0; s < 13; s++) {
        int ph = sched[s];
        int ntok = B_ * ph * ph;
        int sliced = (s < 7);
        if (sliced) {
            int S = 64 / ph + 2;          // safe upper bound on region rows
            int work = ntok * S;
            pool_small_kernel<<<(work + 7) / 8, 256>>>(s, S);
        } else {
            int blocks = (ntok + 7) / 8;
            if (blocks > 1024) blocks = 1024;
            pool_big_kernel<<<blocks, 256>>>(s);
        }
        up_kernel<<<4096, 256>>>(s, sliced);
    }
    loss13_kernel<<<1024, 256>>>();
    if (out_size >= OUT_ELEMS + NSCALES)
        finalize_kernel<<<1, NSCALES * 32>>>(out + OUT_ELEMS);
    gemm_out_kernel<<<512, 256>>>(w_out, b_out, out);
}

// round 7
// speedup vs baseline: 1.6450x; 1.1509x over previous
#include <cuda_runtime.h>
#include <math.h>

#define B_ 16
#define HW 4096          // 64*64
#define CD 32
#define DIMX 512
#define NSCALES 14
#define NPIX (B_*HW)                 // 65536
#define OUT_ELEMS (B_*DIMX*HW)       // 33554432

#define INV_SQRT32 0.17677669529663687f
#define ACOEF 70.710678118654755f    // 4*100/sqrt(32); p = sigmoid(-ACOEF*z)

__device__ float g_r0[NPIX*CD];      // original projection (token-major)
__device__ float g_r [NPIX*CD];      // residual
__device__ float g_part[2][NPIX*CD]; // split-K partials for proj_in
__device__ float g_pool[94720];      // pooled sums, sliced scales 0..6 only
__device__ unsigned g_bits[82720];   // sign bitmaps, scales 7..12
__device__ float g_acc[NSCALES][34]; // [0..31]=sum p, [32]=sum H, [33]=sum commit

__constant__ int c_ph[13]   = {1,2,3,4,5,7,9,12,16,21,27,36,48};
__constant__ int c_poff[7]  = {0,512,2560,7168,15360,28160,53248};    // float pools s<7
__constant__ int c_boff[13] = {0,0,0,0,0,0,0, 0,2304,6400,13456,25120,45856}; // bitmaps s>=7
#define SLICED_POOL_FLOATS 94720

// ---------------------------------------------------------------- f32x2 helpers
__device__ __forceinline__ unsigned long long pk2(float x, float y) {
    unsigned long long r;
    asm("mov.b64 %0, {%1, %2};" : "=l"(r) : "f"(x), "f"(y));
    return r;
}
__device__ __forceinline__ unsigned long long fma2(unsigned long long a,
                                                   unsigned long long b,
                                                   unsigned long long c) {
    unsigned long long d;
    asm("fma.rn.f32x2 %0, %1, %2, %3;" : "=l"(d) : "l"(a), "l"(b), "l"(c));
    return d;
}
__device__ __forceinline__ void upk2(unsigned long long v, float& lo, float& hi) {
    asm("mov.b64 {%0, %1}, %2;" : "=f"(lo), "=f"(hi) : "l"(v));
}

// ---------------------------------------------------------------- init (every replay)
__global__ void init_kernel() {
    int t = blockIdx.x * blockDim.x + threadIdx.x;
    for (int i = t; i < SLICED_POOL_FLOATS; i += gridDim.x * blockDim.x)
        g_pool[i] = 0.f;
    if (t < NSCALES * 34) ((float*)g_acc)[t] = 0.f;
}

// ---------------------------------------------------------------- proj_in GEMM (split-K=2)
__global__ __launch_bounds__(256) void gemm_in_kernel(
        const float* __restrict__ x, const float* __restrict__ w_in) {
    __shared__ float s_w[256 * CD];
    int tid = threadIdx.x;
    int kc = blockIdx.x & 1;
    int pg = blockIdx.x >> 1;
    const float* wsrc = w_in + kc * 256 * CD;
    for (int i = tid; i < 256 * CD; i += 256) s_w[i] = wsrc[i];
    __syncthreads();

    int px = pg * 256 + tid;
    int b = px >> 12, pl = px & 4095;
    const float* xp = x + (size_t)b * (DIMX * HW) + (size_t)(kc * 256) * HW + pl;

    unsigned long long a[16];
#pragma unroll
    for (int i = 0; i < 16; i++) a[i] = 0ull;

#pragma unroll 4
    for (int c = 0; c < 256; c++) {
        float f = xp[(size_t)c * HW];
        unsigned long long X = pk2(f, f);
        const ulonglong2* row = (const ulonglong2*)(s_w + c * CD);
#pragma unroll
        for (int r = 0; r < 8; r++) {
            ulonglong2 w2 = row[r];
            a[2*r]   = fma2(X, w2.x, a[2*r]);
            a[2*r+1] = fma2(X, w2.y, a[2*r+1]);
        }
    }
    ulonglong2* o = (ulonglong2*)(g_part[kc] + (size_t)px * CD);
#pragma unroll
    for (int k = 0; k < 8; k++) {
        ulonglong2 v; v.x = a[2*k]; v.y = a[2*k+1];
        o[k] = v;
    }
}

// combine: r0 = r = part0 + part1 + bias
__global__ __launch_bounds__(256) void combine_kernel(const float* __restrict__ b_in) {
    int idx = blockIdx.x * 256 + threadIdx.x;   // float4 index, grid 2048
    float4 p0 = __ldg((const float4*)g_part[0] + idx);
    float4 p1 = __ldg((const float4*)g_part[1] + idx);
    float4 bi = __ldg((const float4*)b_in + (idx & 7));
    float4 v;
    v.x = p0.x + p1.x + bi.x;
    v.y = p0.y + p1.y + bi.y;
    v.z = p0.z + p1.z + bi.z;
    v.w = p0.w + p1.w + bi.w;
    ((float4*)g_r0)[idx] = v;
    ((float4*)g_r )[idx] = v;
}

// ---------------------------------------------------------------- per-token loss math (lane=d)
__device__ __forceinline__ void loss_token(float ir, float& pa, float& ha, float& ca) {
    float n2 = ir * ir;
#pragma unroll
    for (int o = 16; o > 0; o >>= 1) n2 += __shfl_xor_sync(~0u, n2, o);
    float z = ir / fmaxf(sqrtf(n2), 1e-12f);
    float p = 1.f / (1.f + expf(ACOEF * z));
    float H = -(p * logf(p + 1e-8f) + (1.f - p) * logf(1.f - p + 1e-8f));
    float qv = (z > 0.f) ? INV_SQRT32 : -INV_SQRT32;
    float dz = z - qv;
    pa += p; ha += H; ca += dz * dz;
}

// ---------------------------------------------------------------- pool, big scales (warp/token, fused loss, sign bitmap out)
__global__ __launch_bounds__(256) void pool_big_kernel(int s) {
    __shared__ float s_red[34];
    int tid = threadIdx.x, lane = tid & 31;
    if (tid < 34) s_red[tid] = 0.f;
    __syncthreads();

    int ph = c_ph[s], np = ph * ph, ntok = B_ * np;
    unsigned* bits = g_bits + c_boff[s];
    int gw = blockIdx.x * 8 + (tid >> 5);
    int nw = gridDim.x * 8;

    float pa = 0.f, ha = 0.f, ca = 0.f;
    for (int tok = gw; tok < ntok; tok += nw) {
        int b = tok / np, ij = tok - b * np, i = ij / ph, j = ij - i * ph;
        int sh = (i * 64) / ph, eh = ((i + 1) * 64 + ph - 1) / ph;
        int sw = (j * 64) / ph, ew = ((j + 1) * 64 + ph - 1) / ph;
        const float* rb = g_r + ((size_t)(b * HW)) * CD + lane;
        float sum = 0.f;
        for (int y = sh; y < eh; y++) {
            const float* row = rb + (size_t)(y * 64) * CD;
#pragma unroll 2
            for (int x = sw; x < ew; x++) sum += row[(size_t)x * CD];
        }
        unsigned word = __ballot_sync(~0u, sum > 0.f);
        if (lane == 0) bits[tok] = word;
        loss_token(sum / (float)((eh - sh) * (ew - sw)), pa, ha, ca);
    }
#pragma unroll
    for (int o = 16; o > 0; o >>= 1) {
        ha += __shfl_xor_sync(~0u, ha, o);
        ca += __shfl_xor_sync(~0u, ca, o);
    }
    atomicAdd(&s_red[lane], pa);
    if (lane == 0) { atomicAdd(&s_red[32], ha); atomicAdd(&s_red[33], ca); }
    __syncthreads();
    if (tid < 34) atomicAdd(&g_acc[s][tid], s_red[tid]);
}

// ---------------------------------------------------------------- pool, small scales (row slices, atomic, deep MLP)
__global__ __launch_bounds__(256) void pool_small_kernel(int s, int S) {
    int tid = threadIdx.x, lane = tid & 31;
    int ph = c_ph[s], np = ph * ph, ntok = B_ * np;
    int base = c_poff[s];
    int w = blockIdx.x * 8 + (tid >> 5);
    if (w >= ntok * S) return;
    int tok = w / S, slice = w - tok * S;
    int b = tok / np, ij = tok - b * np, i = ij / ph, j = ij - i * ph;
    int sh = (i * 64) / ph, eh = ((i + 1) * 64 + ph - 1) / ph;
    int y = sh + slice;
    if (y >= eh) return;
    int sw = (j * 64) / ph, ew = ((j + 1) * 64 + ph - 1) / ph;
    const float* row = g_r + ((size_t)(b * HW + y * 64)) * CD + lane;

    float s0 = 0.f, s1 = 0.f, s2 = 0.f, s3 = 0.f;
    int x = sw;
    for (; x + 8 <= ew; x += 8) {
        float a0 = row[(size_t)(x+0) * CD];
        float a1 = row[(size_t)(x+1) * CD];
        float a2 = row[(size_t)(x+2) * CD];
        float a3 = row[(size_t)(x+3) * CD];
        float a4 = row[(size_t)(x+4) * CD];
        float a5 = row[(size_t)(x+5) * CD];
        float a6 = row[(size_t)(x+6) * CD];
        float a7 = row[(size_t)(x+7) * CD];
        s0 += a0 + a4;
        s1 += a1 + a5;
        s2 += a2 + a6;
        s3 += a3 + a7;
    }
    for (; x < ew; x++) s0 += row[(size_t)x * CD];
    float sum = (s0 + s1) + (s2 + s3);
    atomicAdd(&g_pool[base + tok * CD + lane], sum);
}

// ---------------------------------------------------------------- up v2: r -= bilerp(sign(pool)); 4 px/warp, float4 RMW
// grid MUST be 2048 blocks: 2048*8 warps * 4 px/warp = 65536 px
__global__ __launch_bounds__(256) void up_kernel(int s, int sliced) {
    __shared__ int s_i0[64], s_i1[64];
    __shared__ float s_f[64];
    __shared__ float s_red[34];
    int tid = threadIdx.x, lane = tid & 31;
    int ph = c_ph[s], np = ph * ph;

    if (tid < 64) {
        float src = ((float)tid + 0.5f) * (float)ph * 0.015625f - 0.5f;
        src = fminf(fmaxf(src, 0.f), (float)(ph - 1));
        int i0 = (int)src;
        s_i0[tid] = i0;
        s_i1[tid] = min(i0 + 1, ph - 1);
        s_f[tid]  = src - (float)i0;
    }
    if (tid < 34) s_red[tid] = 0.f;
    __syncthreads();

    int gw = blockIdx.x * 8 + (tid >> 5);          // 16384 warps total

    if (sliced) {
        int ntok = B_ * np;
        if (gw < ntok) {
            const float* pool = g_pool + c_poff[s];
            int tok = gw;
            int b = tok / np, ij = tok - b * np, i = ij / ph, j = ij - i * ph;
            int ah = ((i + 1) * 64 + ph - 1) / ph - (i * 64) / ph;
            int aw = ((j + 1) * 64 + ph - 1) / ph - (j * 64) / ph;
            float ir = pool[tok * CD + lane] / (float)(ah * aw);
            float pa = 0.f, ha = 0.f, ca = 0.f;
            loss_token(ir, pa, ha, ca);
#pragma unroll
            for (int o = 16; o > 0; o >>= 1) {
                ha += __shfl_xor_sync(~0u, ha, o);
                ca += __shfl_xor_sync(~0u, ca, o);
            }
            atomicAdd(&s_red[lane], pa);
            if (lane == 0) { atomicAdd(&s_red[32], ha); atomicAdd(&s_red[33], ca); }
        }
    }

    // pixel work: lane = sub(2b) * 8 + q(3b); px = gw*4+sub, d = 4q..4q+3
    int sub = lane >> 3, q = lane & 7;
    int px = gw * 4 + sub;
    int b = px >> 12, h = (px >> 6) & 63, w = px & 63;
    int i0 = s_i0[h], i1 = s_i1[h]; float fh = s_f[h];
    int j0 = s_i0[w], j1 = s_i1[w]; float fw = s_f[w];
    int tb = b * np;
    int t00 = tb + i0 * ph + j0, t01 = tb + i0 * ph + j1;
    int t10 = tb + i1 * ph + j0, t11 = tb + i1 * ph + j1;

    float v[4];
    if (s >= 7) {
        const unsigned* bits = g_bits + c_boff[s];
        unsigned w00 = bits[t00], w01 = bits[t01];
        unsigned w10 = bits[t10], w11 = bits[t11];
#pragma unroll
        for (int k = 0; k < 4; k++) {
            int d = 4 * q + k;
            float s00 = ((w00 >> d) & 1u) ? 1.f : -1.f;
            float s01 = ((w01 >> d) & 1u) ? 1.f : -1.f;
            float s10 = ((w10 >> d) & 1u) ? 1.f : -1.f;
            float s11 = ((w11 >> d) & 1u) ? 1.f : -1.f;
            float top = s00 + fw * (s01 - s00);
            float bot = s10 + fw * (s11 - s10);
            v[k] = INV_SQRT32 * (top + fh * (bot - top));
        }
    } else {
        const float* pool = g_pool + c_poff[s];
        float4 p00 = *(const float4*)(pool + t00 * CD + 4 * q);
        float4 p01 = *(const float4*)(pool + t01 * CD + 4 * q);
        float4 p10 = *(const float4*)(pool + t10 * CD + 4 * q);
        float4 p11 = *(const float4*)(pool + t11 * CD + 4 * q);
        const float* a00 = (const float*)&p00;
        const float* a01 = (const float*)&p01;
        const float* a10 = (const float*)&p10;
        const float* a11 = (const float*)&p11;
#pragma unroll
        for (int k = 0; k < 4; k++) {
            float s00 = a00[k] > 0.f ? 1.f : -1.f;
            float s01 = a01[k] > 0.f ? 1.f : -1.f;
            float s10 = a10[k] > 0.f ? 1.f : -1.f;
            float s11 = a11[k] > 0.f ? 1.f : -1.f;
            float top = s00 + fw * (s01 - s00);
            float bot = s10 + fw * (s11 - s10);
            v[k] = INV_SQRT32 * (top + fh * (bot - top));
        }
    }

    float4* rp = (float4*)(g_r + (size_t)px * CD + 4 * q);
    float4 rv = *rp;
    rv.x -= v[0]; rv.y -= v[1]; rv.z -= v[2]; rv.w -= v[3];
    *rp = rv;

    if (sliced) {
        __syncthreads();
        if (tid < 34) atomicAdd(&g_acc[s][tid], s_red[tid]);
    }
}

// ---------------------------------------------------------------- loss for scale 13 (identity, reads r)
__global__ __launch_bounds__(256) void loss13_kernel() {
    __shared__ float s_red[34];
    int tid = threadIdx.x, lane = tid & 31;
    if (tid < 34) s_red[tid] = 0.f;
    __syncthreads();
    int gw = blockIdx.x * 8 + (tid >> 5);
    int nw = gridDim.x * 8;
    float pa = 0.f, ha = 0.f, ca = 0.f;
    for (int tok = gw; tok < NPIX; tok += nw) {
        float ir = g_r[(size_t)tok * CD + lane];
        loss_token(ir, pa, ha, ca);
    }
#pragma unroll
    for (int o = 16; o > 0; o >>= 1) {
        ha += __shfl_xor_sync(~0u, ha, o);
        ca += __shfl_xor_sync(~0u, ca, o);
    }
    atomicAdd(&s_red[lane], pa);
    if (lane == 0) { atomicAdd(&s_red[32], ha); atomicAdd(&s_red[33], ca); }
    __syncthreads();
    if (tid < 34) atomicAdd(&g_acc[13][tid], s_red[tid]);
}

// ---------------------------------------------------------------- finalize losses
__global__ void finalize_kernel(float* __restrict__ loss_out) {
    int s = threadIdx.x >> 5;
    int lane = threadIdx.x & 31;
    if (s >= NSCALES) return;
    int ph = (s < 13) ? c_ph[s] : 64;
    float n = (float)(B_ * ph * ph);
    float ap = g_acc[s][lane] / n;
    float H = -(ap * logf(ap + 1e-8f) + (1.f - ap) * logf(1.f - ap + 1e-8f));
#pragma unroll
    for (int o = 16; o > 0; o >>= 1) H += __shfl_xor_sync(~0u, H, o);
    if (lane == 0) {
        float ps = g_acc[s][32] / n;
        float cm = g_acc[s][33] / (n * 32.f);
        loss_out[s] = (ps - H) * (0.1f / 100.f) + 0.25f * cm;
    }
}

// ---------------------------------------------------------------- proj_out GEMM (split-N=2)
__global__ __launch_bounds__(256) void gemm_out_kernel(
        const float* __restrict__ w_out,
        const float* __restrict__ b_out,
        float* __restrict__ out) {
    __shared__ float s_wt[256 * 36];
    __shared__ float s_b[256];
    int tid = threadIdx.x;
    int kc = blockIdx.x & 1;
    int pg = blockIdx.x >> 1;
    int c0 = kc * 256;
    for (int i = tid; i < 256 * CD; i += 256) {
        int d = i >> 8, c = i & 255;
        s_wt[c * 36 + d] = w_out[d * DIMX + c0 + c];
    }
    if (tid < 256) s_b[tid] = b_out[c0 + tid];
    __syncthreads();

    int px = pg * 256 + tid;
    int b = px >> 12, pl = px & 4095;
    size_t o = (size_t)px * CD;

    unsigned long long Q[16];
#pragma unroll
    for (int k = 0; k < 8; k++) {
        float4 a = __ldg((const float4*)(g_r0 + o) + k);
        float4 r = ((const float4*)(g_r + o))[k];
        float qx = (r.x > 0.f) ? INV_SQRT32 : -INV_SQRT32;
        float qy = (r.y > 0.f) ? INV_SQRT32 : -INV_SQRT32;
        float qz = (r.z > 0.f) ? INV_SQRT32 : -INV_SQRT32;
        float qw = (r.w > 0.f) ? INV_SQRT32 : -INV_SQRT32;
        Q[2*k]   = pk2(a.x - r.x + qx, a.y - r.y + qy);
        Q[2*k+1] = pk2(a.z - r.z + qz, a.w - r.w + qw);
    }

    float* op = out + (size_t)b * (DIMX * HW) + (size_t)c0 * HW + pl;
#pragma unroll 2
    for (int c = 0; c < 256; c++) {
        const ulonglong2* wrow = (const ulonglong2*)(s_wt + c * 36);
        unsigned long long ae = 0, ao = 0;
#pragma unroll
        for (int r = 0; r < 8; r++) {
            ulonglong2 W = wrow[r];
            ae = fma2(Q[2*r],   W.x, ae);
            ao = fma2(Q[2*r+1], W.y, ao);
        }
        float lo, hi, sum;
        upk2(ae, lo, hi); sum = lo + hi;
        upk2(ao, lo, hi); sum += lo + hi;
        op[(size_t)c * HW] = sum + s_b[c];
    }
}

// ---------------------------------------------------------------- launch
extern "C" void kernel_launch(void* const* d_in, const int* in_sizes, int n_in,
                              void* d_out, int out_size) {
    const float* x     = (const float*)d_in[0];
    const float* w_in  = (const float*)d_in[1];
    const float* b_in  = (const float*)d_in[2];
    const float* w_out = (const float*)d_in[3];
    const float* b_out = (const float*)d_in[4];
    float* out = (float*)d_out;

    static const int sched[13] = {1,2,3,4,5,7,9,12,16,21,27,36,48};

    init_kernel<<<370, 256>>>();
    gemm_in_kernel<<<512, 256>>>(x, w_in);
    combine_kernel<<<2048, 256>>>(b_in);

    for (int s = 0; s < 13; s++) {
        int ph = sched[s];
        int ntok = B_ * ph * ph;
        int sliced = (s < 7);
        if (sliced) {
            int S = 64 / ph + 2;          // safe upper bound on region rows
            int work = ntok * S;
            pool_small_kernel<<<(work + 7) / 8, 256>>>(s, S);
        } else {
            int blocks = (ntok + 7) / 8;
            if (blocks > 1024) blocks = 1024;
            pool_big_kernel<<<blocks, 256>>>(s);
        }
        up_kernel<<<2048, 256>>>(s, sliced);
    }
    loss13_kernel<<<1024, 256>>>();
    if (out_size >= OUT_ELEMS + NSCALES)
        finalize_kernel<<<1, NSCALES * 32>>>(out + OUT_ELEMS);
    gemm_out_kernel<<<512, 256>>>(w_out, b_out, out);
}